// round 4
// baseline (speedup 1.0000x reference)
#include <cuda_runtime.h>
#include <cstdint>
#include <cmath>

#define BATCH 4
#define SEQ   2048
#define EMB   1024
#define HEADS 16
#define HDIM  64
#define MROWS (BATCH*SEQ)   // 8192

// Scratch (no allocations allowed)
__device__ float g_q[BATCH*HEADS*SEQ*HDIM];
__device__ float g_k[BATCH*HEADS*SEQ*HDIM];
__device__ float g_v[BATCH*HEADS*SEQ*HDIM];
__device__ float g_ao[BATCH*SEQ*EMB];

// ---------------------------------------------------------------------------
// helpers
// ---------------------------------------------------------------------------
__device__ __forceinline__ uint32_t tf32_rna(float x) {
    uint32_t r;
    asm("cvt.rna.tf32.f32 %0, %1;" : "=r"(r) : "f"(x));
    return r;
}
__device__ __forceinline__ void tf32_split(float x, uint32_t& hi, uint32_t& lo) {
    hi = tf32_rna(x);
    lo = tf32_rna(x - __uint_as_float(hi));
}
__device__ __forceinline__ void mma_tf32(float* c, const uint32_t* a, const uint32_t* b) {
    asm volatile(
        "mma.sync.aligned.m16n8k8.row.col.f32.tf32.tf32.f32 "
        "{%0,%1,%2,%3}, {%4,%5,%6,%7}, {%8,%9}, {%0,%1,%2,%3};"
        : "+f"(c[0]), "+f"(c[1]), "+f"(c[2]), "+f"(c[3])
        : "r"(a[0]), "r"(a[1]), "r"(a[2]), "r"(a[3]), "r"(b[0]), "r"(b[1]));
}

// ---------------------------------------------------------------------------
// 3xTF32 GEMM: C = A[M,K] @ B[K,N] + bias.  Tile 128x128x16, 256 thr, 8 warps.
// warp layout 4(m) x 2(n): each warp 32 rows x 64 cols.
// ---------------------------------------------------------------------------
__global__ __launch_bounds__(256)
void gemm_tf32(const float* __restrict__ A, const float* __restrict__ Bm,
               const float* __restrict__ bias, float* __restrict__ C,
               int M, int N, int K, int headsplit)
{
    __shared__ __align__(16) float As[128][20];
    __shared__ __align__(16) float Bs[16][136];

    const int tid  = threadIdx.x;
    const int wid  = tid >> 5;
    const int lane = tid & 31;
    const int gid  = lane >> 2;   // 0..7
    const int tig  = lane & 3;    // 0..3
    const int wm   = wid >> 1;    // 0..3
    const int wn   = wid & 1;     // 0..1
    const int row0 = blockIdx.y * 128;
    const int col0 = blockIdx.x * 128;

    float c[2][8][4];
#pragma unroll
    for (int mt = 0; mt < 2; mt++)
#pragma unroll
        for (int nt = 0; nt < 8; nt++)
#pragma unroll
            for (int i = 0; i < 4; i++) c[mt][nt][i] = 0.f;

    const int ar = tid >> 1, ac = (tid & 1) * 8;
    const int br = tid >> 4, bc = (tid & 15) * 8;

    const float* Abase = A + (size_t)(row0 + ar) * K + ac;
    const float* Bbase = Bm + (size_t)br * N + col0 + bc;

    float4 aR0 = *(const float4*)(Abase);
    float4 aR1 = *(const float4*)(Abase + 4);
    float4 bR0 = *(const float4*)(Bbase);
    float4 bR1 = *(const float4*)(Bbase + 4);

    for (int k0 = 0; k0 < K; k0 += 16) {
        *(float4*)&As[ar][ac]     = aR0;
        *(float4*)&As[ar][ac + 4] = aR1;
        *(float4*)&Bs[br][bc]     = bR0;
        *(float4*)&Bs[br][bc + 4] = bR1;
        __syncthreads();

        if (k0 + 16 < K) {
            aR0 = *(const float4*)(Abase + k0 + 16);
            aR1 = *(const float4*)(Abase + k0 + 20);
            bR0 = *(const float4*)(Bbase + (size_t)(k0 + 16) * N);
            bR1 = *(const float4*)(Bbase + (size_t)(k0 + 16) * N + 4);
        }

#pragma unroll
        for (int ks = 0; ks < 2; ks++) {
            uint32_t ahi[2][4], alo[2][4];
#pragma unroll
            for (int mt = 0; mt < 2; mt++) {
                const int m0 = wm * 32 + mt * 16;
                float x0 = As[m0 + gid    ][ks * 8 + tig];
                float x1 = As[m0 + gid + 8][ks * 8 + tig];
                float x2 = As[m0 + gid    ][ks * 8 + tig + 4];
                float x3 = As[m0 + gid + 8][ks * 8 + tig + 4];
                tf32_split(x0, ahi[mt][0], alo[mt][0]);
                tf32_split(x1, ahi[mt][1], alo[mt][1]);
                tf32_split(x2, ahi[mt][2], alo[mt][2]);
                tf32_split(x3, ahi[mt][3], alo[mt][3]);
            }
#pragma unroll
            for (int nt = 0; nt < 8; nt++) {
                const int n0 = wn * 64 + nt * 8;
                float y0 = Bs[ks * 8 + tig    ][n0 + gid];
                float y1 = Bs[ks * 8 + tig + 4][n0 + gid];
                uint32_t bhi[2], blo[2];
                tf32_split(y0, bhi[0], blo[0]);
                tf32_split(y1, bhi[1], blo[1]);
#pragma unroll
                for (int mt = 0; mt < 2; mt++) {
                    mma_tf32(c[mt][nt], ahi[mt], bhi);
                    mma_tf32(c[mt][nt], alo[mt], bhi);
                    mma_tf32(c[mt][nt], ahi[mt], blo);
                }
            }
        }
        __syncthreads();
    }

    // epilogue
#pragma unroll
    for (int mt = 0; mt < 2; mt++) {
        const int m_lo = row0 + wm * 32 + mt * 16 + gid;
        const int m_hi = m_lo + 8;
#pragma unroll
        for (int nt = 0; nt < 8; nt++) {
            const int n = col0 + wn * 64 + nt * 8 + 2 * tig;
            const float b0 = bias[n], b1 = bias[n + 1];
            float v00 = c[mt][nt][0] + b0, v01 = c[mt][nt][1] + b1;
            float v10 = c[mt][nt][2] + b0, v11 = c[mt][nt][3] + b1;
            if (headsplit) {
                const int b_lo = m_lo / SEQ, s_lo = m_lo % SEQ;
                const int b_hi = m_hi / SEQ, s_hi = m_hi % SEQ;
                const int h = n / HDIM, d = n % HDIM;
                C[(((size_t)(b_lo*HEADS + h))*SEQ + s_lo)*HDIM + d    ] = v00;
                C[(((size_t)(b_lo*HEADS + h))*SEQ + s_lo)*HDIM + d + 1] = v01;
                C[(((size_t)(b_hi*HEADS + h))*SEQ + s_hi)*HDIM + d    ] = v10;
                C[(((size_t)(b_hi*HEADS + h))*SEQ + s_hi)*HDIM + d + 1] = v11;
            } else {
                C[(size_t)m_lo * N + n    ] = v00;
                C[(size_t)m_lo * N + n + 1] = v01;
                C[(size_t)m_hi * N + n    ] = v10;
                C[(size_t)m_hi * N + n + 1] = v11;
            }
        }
    }
}

// ---------------------------------------------------------------------------
// Causal flash attention with 3xTF32 mma.
// Block: 64 q-rows of one (b,h); 4 warps, warp w owns rows [w*16, w*16+16).
// Key chunks of 32.
// ---------------------------------------------------------------------------
__global__ __launch_bounds__(128)
void attn_tf32(const float* __restrict__ Q, const float* __restrict__ Kg,
               const float* __restrict__ Vg, float* __restrict__ O)
{
    __shared__ __align__(16) float Qs[64][68];
    __shared__ __align__(16) float Ks[32][68];
    __shared__ __align__(16) float Vs[32][72];
    __shared__ float Ss[64][36];
    __shared__ float mrow[64], lrow[64], srow[64];

    const int bh  = blockIdx.y;
    const int qt  = blockIdx.x;
    const int tid = threadIdx.x;
    const int wid = tid >> 5;
    const int lane = tid & 31;
    const int gid = lane >> 2;
    const int tig = lane & 3;
    const int m0  = wid * 16;

    const float* Qbase = Q + ((size_t)bh * SEQ + qt * 64) * HDIM;
    const float* Kbase = Kg + (size_t)bh * SEQ * HDIM;
    const float* Vbase = Vg + (size_t)bh * SEQ * HDIM;

    // stage Q tile (64x64)
    {
        const int qr = tid >> 1, qc = (tid & 1) * 32;
#pragma unroll
        for (int i = 0; i < 8; i++)
            *(float4*)&Qs[qr][qc + i * 4] = *(const float4*)(Qbase + (size_t)qr * HDIM + qc + i * 4);
    }
    if (tid < 64) { mrow[tid] = -INFINITY; lrow[tid] = 0.f; }
    __syncthreads();

    // Q fragments (scaled by 1/sqrt(D) = 0.125), hi/lo split, in registers
    uint32_t qhi[8][4], qlo[8][4];
#pragma unroll
    for (int ks = 0; ks < 8; ks++) {
        float x0 = Qs[m0 + gid    ][ks * 8 + tig]     * 0.125f;
        float x1 = Qs[m0 + gid + 8][ks * 8 + tig]     * 0.125f;
        float x2 = Qs[m0 + gid    ][ks * 8 + tig + 4] * 0.125f;
        float x3 = Qs[m0 + gid + 8][ks * 8 + tig + 4] * 0.125f;
        tf32_split(x0, qhi[ks][0], qlo[ks][0]);
        tf32_split(x1, qhi[ks][1], qlo[ks][1]);
        tf32_split(x2, qhi[ks][2], qlo[ks][2]);
        tf32_split(x3, qhi[ks][3], qlo[ks][3]);
    }

    float o[8][4];
#pragma unroll
    for (int nt = 0; nt < 8; nt++)
#pragma unroll
        for (int i = 0; i < 4; i++) o[nt][i] = 0.f;

    const int cmax = 2 * qt + 1;   // chunks of 32 keys
    for (int ch = 0; ch <= cmax; ch++) {
        // stage K,V chunk (32x64 each)
        {
            const int kr = tid >> 2, kc = (tid & 3) * 16;
            const float* kp = Kbase + (size_t)(ch * 32 + kr) * HDIM + kc;
            const float* vp = Vbase + (size_t)(ch * 32 + kr) * HDIM + kc;
#pragma unroll
            for (int i = 0; i < 4; i++) {
                *(float4*)&Ks[kr][kc + i * 4] = *(const float4*)(kp + i * 4);
                *(float4*)&Vs[kr][kc + i * 4] = *(const float4*)(vp + i * 4);
            }
        }
        __syncthreads();

        // S = Q K^T (16x32 per warp)
        float s[4][4];
#pragma unroll
        for (int nt = 0; nt < 4; nt++)
#pragma unroll
            for (int i = 0; i < 4; i++) s[nt][i] = 0.f;
#pragma unroll
        for (int ks = 0; ks < 8; ks++) {
#pragma unroll
            for (int nt = 0; nt < 4; nt++) {
                float y0 = Ks[nt * 8 + gid][ks * 8 + tig];
                float y1 = Ks[nt * 8 + gid][ks * 8 + tig + 4];
                uint32_t bhi[2], blo[2];
                tf32_split(y0, bhi[0], blo[0]);
                tf32_split(y1, bhi[1], blo[1]);
                mma_tf32(s[nt], qhi[ks], bhi);
                mma_tf32(s[nt], qlo[ks], bhi);
                mma_tf32(s[nt], qhi[ks], blo);
            }
        }
        // write S to SMEM
#pragma unroll
        for (int nt = 0; nt < 4; nt++) {
            const int cc = nt * 8 + 2 * tig;
            Ss[m0 + gid    ][cc]     = s[nt][0];
            Ss[m0 + gid    ][cc + 1] = s[nt][1];
            Ss[m0 + gid + 8][cc]     = s[nt][2];
            Ss[m0 + gid + 8][cc + 1] = s[nt][3];
        }
        __syncthreads();

        // online softmax: warp handles its 16 rows serially, lanes over 32 keys
#pragma unroll 1
        for (int i = 0; i < 16; i++) {
            const int r = m0 + i;
            const int qrow = qt * 64 + r;
            const int key  = ch * 32 + lane;
            float sc = (key <= qrow) ? Ss[r][lane] : -INFINITY;
            float mx = sc;
#pragma unroll
            for (int off = 16; off > 0; off >>= 1)
                mx = fmaxf(mx, __shfl_xor_sync(0xffffffffu, mx, off));
            const float mold = mrow[r];
            const float mnew = fmaxf(mold, mx);
            const float p = __expf(sc - mnew);
            float ps = p;
#pragma unroll
            for (int off = 16; off > 0; off >>= 1)
                ps += __shfl_xor_sync(0xffffffffu, ps, off);
            if (lane == 0) {
                const float corr = __expf(mold - mnew);
                lrow[r] = lrow[r] * corr + ps;
                srow[r] = corr;
                mrow[r] = mnew;
            }
            Ss[r][lane] = p;
        }
        __syncthreads();

        // rescale O, then O += P V
        {
            const float s0 = srow[m0 + gid];
            const float s1 = srow[m0 + 8 + gid];
#pragma unroll
            for (int nt = 0; nt < 8; nt++) {
                o[nt][0] *= s0; o[nt][1] *= s0;
                o[nt][2] *= s1; o[nt][3] *= s1;
            }
        }
#pragma unroll
        for (int ks = 0; ks < 4; ks++) {
            uint32_t phi[4], plo[4];
            {
                float x0 = Ss[m0 + gid    ][ks * 8 + tig];
                float x1 = Ss[m0 + gid + 8][ks * 8 + tig];
                float x2 = Ss[m0 + gid    ][ks * 8 + tig + 4];
                float x3 = Ss[m0 + gid + 8][ks * 8 + tig + 4];
                tf32_split(x0, phi[0], plo[0]);
                tf32_split(x1, phi[1], plo[1]);
                tf32_split(x2, phi[2], plo[2]);
                tf32_split(x3, phi[3], plo[3]);
            }
#pragma unroll
            for (int nt = 0; nt < 8; nt++) {
                float y0 = Vs[ks * 8 + tig    ][nt * 8 + gid];
                float y1 = Vs[ks * 8 + tig + 4][nt * 8 + gid];
                uint32_t vhi[2], vlo[2];
                tf32_split(y0, vhi[0], vlo[0]);
                tf32_split(y1, vhi[1], vlo[1]);
                mma_tf32(o[nt], phi, vhi);
                mma_tf32(o[nt], plo, vhi);
                mma_tf32(o[nt], phi, vlo);
            }
        }
        __syncthreads();
    }

    // epilogue: normalize and store to [b][s][h*64+d]
    const float inv0 = 1.f / lrow[m0 + gid];
    const float inv1 = 1.f / lrow[m0 + 8 + gid];
    const int b = bh / HEADS, h = bh % HEADS;
    const int sg0 = qt * 64 + m0 + gid;
    float* orow0 = O + ((size_t)(b * SEQ + sg0    )) * EMB + h * HDIM;
    float* orow1 = O + ((size_t)(b * SEQ + sg0 + 8)) * EMB + h * HDIM;
#pragma unroll
    for (int nt = 0; nt < 8; nt++) {
        const int cc = nt * 8 + 2 * tig;
        orow0[cc]     = o[nt][0] * inv0;
        orow0[cc + 1] = o[nt][1] * inv0;
        orow1[cc]     = o[nt][2] * inv1;
        orow1[cc + 1] = o[nt][3] * inv1;
    }
}

// ---------------------------------------------------------------------------
extern "C" void kernel_launch(void* const* d_in, const int* in_sizes, int n_in,
                              void* d_out, int out_size)
{
    const float* x  = (const float*)d_in[0];
    const float* Wq = (const float*)d_in[1];
    const float* bq = (const float*)d_in[2];
    const float* Wk = (const float*)d_in[3];
    const float* bk = (const float*)d_in[4];
    const float* Wv = (const float*)d_in[5];
    const float* bv = (const float*)d_in[6];
    const float* Wo = (const float*)d_in[7];
    const float* bo = (const float*)d_in[8];
    float* out = (float*)d_out;

    float *q_ptr, *k_ptr, *v_ptr, *ao_ptr;
    cudaGetSymbolAddress((void**)&q_ptr,  g_q);
    cudaGetSymbolAddress((void**)&k_ptr,  g_k);
    cudaGetSymbolAddress((void**)&v_ptr,  g_v);
    cudaGetSymbolAddress((void**)&ao_ptr, g_ao);

    dim3 gblk(256);
    dim3 ggrid(EMB / 128, MROWS / 128);   // (8, 64)

    gemm_tf32<<<ggrid, gblk>>>(x, Wq, bq, q_ptr, MROWS, EMB, EMB, 1);
    gemm_tf32<<<ggrid, gblk>>>(x, Wk, bk, k_ptr, MROWS, EMB, EMB, 1);
    gemm_tf32<<<ggrid, gblk>>>(x, Wv, bv, v_ptr, MROWS, EMB, EMB, 1);

    dim3 agrid(SEQ / 64, BATCH * HEADS);  // (32, 64)
    attn_tf32<<<agrid, 128>>>(q_ptr, k_ptr, v_ptr, ao_ptr);

    gemm_tf32<<<ggrid, gblk>>>(ao_ptr, Wo, bo, out, MROWS, EMB, EMB, 0);
}

// round 5
// speedup vs baseline: 1.4327x; 1.4327x over previous
#include <cuda_runtime.h>
#include <cstdint>
#include <cmath>

#define BATCH 4
#define SEQ   2048
#define EMB   1024
#define HEADS 16
#define HDIM  64
#define MROWS (BATCH*SEQ)   // 8192

// Scratch (no allocations allowed)
__device__ float g_q[BATCH*HEADS*SEQ*HDIM];
__device__ float g_k[BATCH*HEADS*SEQ*HDIM];
__device__ float g_v[BATCH*HEADS*SEQ*HDIM];
__device__ float g_ao[BATCH*SEQ*EMB];

// ---------------------------------------------------------------------------
// helpers
// ---------------------------------------------------------------------------
__device__ __forceinline__ uint32_t tf32_rna(float x) {
    uint32_t r;
    asm("cvt.rna.tf32.f32 %0, %1;" : "=r"(r) : "f"(x));
    return r;
}
__device__ __forceinline__ void tf32_split(float x, uint32_t& hi, uint32_t& lo) {
    hi = tf32_rna(x);
    lo = tf32_rna(x - __uint_as_float(hi));
}
__device__ __forceinline__ void split4(const float4 v, float4& hi, float4& lo) {
    uint32_t h, l;
    tf32_split(v.x, h, l); hi.x = __uint_as_float(h); lo.x = __uint_as_float(l);
    tf32_split(v.y, h, l); hi.y = __uint_as_float(h); lo.y = __uint_as_float(l);
    tf32_split(v.z, h, l); hi.z = __uint_as_float(h); lo.z = __uint_as_float(l);
    tf32_split(v.w, h, l); hi.w = __uint_as_float(h); lo.w = __uint_as_float(l);
}
__device__ __forceinline__ void mma_tf32(float* c, const uint32_t* a, const uint32_t* b) {
    asm volatile(
        "mma.sync.aligned.m16n8k8.row.col.f32.tf32.tf32.f32 "
        "{%0,%1,%2,%3}, {%4,%5,%6,%7}, {%8,%9}, {%0,%1,%2,%3};"
        : "+f"(c[0]), "+f"(c[1]), "+f"(c[2]), "+f"(c[3])
        : "r"(a[0]), "r"(a[1]), "r"(a[2]), "r"(a[3]), "r"(b[0]), "r"(b[1]));
}
__device__ __forceinline__ float fbits(const float* p) { return *p; }

// ---------------------------------------------------------------------------
// 3xTF32 GEMM, pre-split SMEM. C = A[M,K]@B[K,N] + bias. 128x128x16, 256 thr.
// warp layout 4(m) x 2(n): warp = 32 rows x 64 cols.
// ---------------------------------------------------------------------------
__global__ __launch_bounds__(256)
void gemm_tf32(const float* __restrict__ A, const float* __restrict__ Bm,
               const float* __restrict__ bias, float* __restrict__ C,
               int M, int N, int K, int headsplit)
{
    __shared__ __align__(16) float Ahi[128][20];
    __shared__ __align__(16) float Alo[128][20];
    __shared__ __align__(16) float Bhi[16][136];
    __shared__ __align__(16) float Blo[16][136];

    const int tid  = threadIdx.x;
    const int wid  = tid >> 5;
    const int lane = tid & 31;
    const int gid  = lane >> 2;
    const int tig  = lane & 3;
    const int wm   = wid >> 1;
    const int wn   = wid & 1;
    const int row0 = blockIdx.y * 128;
    const int col0 = blockIdx.x * 128;

    float c[2][8][4];
#pragma unroll
    for (int mt = 0; mt < 2; mt++)
#pragma unroll
        for (int nt = 0; nt < 8; nt++)
#pragma unroll
            for (int i = 0; i < 4; i++) c[mt][nt][i] = 0.f;

    const int ar = tid >> 1, ac = (tid & 1) * 8;
    const int br = tid >> 4, bc = (tid & 15) * 8;

    const float* Abase = A + (size_t)(row0 + ar) * K + ac;
    const float* Bbase = Bm + (size_t)br * N + col0 + bc;

    float4 aR0 = *(const float4*)(Abase);
    float4 aR1 = *(const float4*)(Abase + 4);
    float4 bR0 = *(const float4*)(Bbase);
    float4 bR1 = *(const float4*)(Bbase + 4);

    for (int k0 = 0; k0 < K; k0 += 16) {
        float4 h, l;
        split4(aR0, h, l); *(float4*)&Ahi[ar][ac]   = h; *(float4*)&Alo[ar][ac]   = l;
        split4(aR1, h, l); *(float4*)&Ahi[ar][ac+4] = h; *(float4*)&Alo[ar][ac+4] = l;
        split4(bR0, h, l); *(float4*)&Bhi[br][bc]   = h; *(float4*)&Blo[br][bc]   = l;
        split4(bR1, h, l); *(float4*)&Bhi[br][bc+4] = h; *(float4*)&Blo[br][bc+4] = l;
        __syncthreads();

        if (k0 + 16 < K) {
            aR0 = *(const float4*)(Abase + k0 + 16);
            aR1 = *(const float4*)(Abase + k0 + 20);
            bR0 = *(const float4*)(Bbase + (size_t)(k0 + 16) * N);
            bR1 = *(const float4*)(Bbase + (size_t)(k0 + 16) * N + 4);
        }

#pragma unroll
        for (int ks = 0; ks < 2; ks++) {
            uint32_t ahi[2][4], alo[2][4];
#pragma unroll
            for (int mt = 0; mt < 2; mt++) {
                const int m0 = wm * 32 + mt * 16;
                ahi[mt][0] = __float_as_uint(Ahi[m0 + gid    ][ks*8 + tig]);
                ahi[mt][1] = __float_as_uint(Ahi[m0 + gid + 8][ks*8 + tig]);
                ahi[mt][2] = __float_as_uint(Ahi[m0 + gid    ][ks*8 + tig + 4]);
                ahi[mt][3] = __float_as_uint(Ahi[m0 + gid + 8][ks*8 + tig + 4]);
                alo[mt][0] = __float_as_uint(Alo[m0 + gid    ][ks*8 + tig]);
                alo[mt][1] = __float_as_uint(Alo[m0 + gid + 8][ks*8 + tig]);
                alo[mt][2] = __float_as_uint(Alo[m0 + gid    ][ks*8 + tig + 4]);
                alo[mt][3] = __float_as_uint(Alo[m0 + gid + 8][ks*8 + tig + 4]);
            }
#pragma unroll
            for (int nt = 0; nt < 8; nt++) {
                const int n0 = wn * 64 + nt * 8;
                uint32_t bh[2], bl[2];
                bh[0] = __float_as_uint(Bhi[ks*8 + tig    ][n0 + gid]);
                bh[1] = __float_as_uint(Bhi[ks*8 + tig + 4][n0 + gid]);
                bl[0] = __float_as_uint(Blo[ks*8 + tig    ][n0 + gid]);
                bl[1] = __float_as_uint(Blo[ks*8 + tig + 4][n0 + gid]);
#pragma unroll
                for (int mt = 0; mt < 2; mt++) {
                    mma_tf32(c[mt][nt], ahi[mt], bh);
                    mma_tf32(c[mt][nt], alo[mt], bh);
                    mma_tf32(c[mt][nt], ahi[mt], bl);
                }
            }
        }
        __syncthreads();
    }

#pragma unroll
    for (int mt = 0; mt < 2; mt++) {
        const int m_lo = row0 + wm * 32 + mt * 16 + gid;
        const int m_hi = m_lo + 8;
#pragma unroll
        for (int nt = 0; nt < 8; nt++) {
            const int n = col0 + wn * 64 + nt * 8 + 2 * tig;
            const float b0 = bias[n], b1 = bias[n + 1];
            float v00 = c[mt][nt][0] + b0, v01 = c[mt][nt][1] + b1;
            float v10 = c[mt][nt][2] + b0, v11 = c[mt][nt][3] + b1;
            if (headsplit) {
                const int b_lo = m_lo / SEQ, s_lo = m_lo % SEQ;
                const int b_hi = m_hi / SEQ, s_hi = m_hi % SEQ;
                const int h = n / HDIM, d = n % HDIM;
                C[(((size_t)(b_lo*HEADS + h))*SEQ + s_lo)*HDIM + d    ] = v00;
                C[(((size_t)(b_lo*HEADS + h))*SEQ + s_lo)*HDIM + d + 1] = v01;
                C[(((size_t)(b_hi*HEADS + h))*SEQ + s_hi)*HDIM + d    ] = v10;
                C[(((size_t)(b_hi*HEADS + h))*SEQ + s_hi)*HDIM + d + 1] = v11;
            } else {
                C[(size_t)m_lo * N + n    ] = v00;
                C[(size_t)m_lo * N + n + 1] = v01;
                C[(size_t)m_hi * N + n    ] = v10;
                C[(size_t)m_hi * N + n + 1] = v11;
            }
        }
    }
}

// ---------------------------------------------------------------------------
// Causal flash attention v3, 3xTF32.
// Block: 128 q-rows, 128 threads, 4 warps; warp owns 32 rows (2 m-tiles).
// Key chunks of 32, K/V pre-split hi/lo, register softmax, per-warp P buffer.
// ---------------------------------------------------------------------------
#define QS(r,c)    sQ[(r)*68 + (c)]
#define KHI(r,c)   sKh[(r)*68 + (c)]
#define KLO(r,c)   sKl[(r)*68 + (c)]
#define VHI(r,c)   sVh[(r)*72 + (c)]
#define VLO(r,c)   sVl[(r)*72 + (c)]
#define SSW(cc,rr) sP[(cc)*36 + (rr)]

#define ATTN_SMEM_FLOATS (128*68 + 2*32*68 + 2*32*72 + 4*32*36)

__global__ __launch_bounds__(128)
void attn_tf32(const float* __restrict__ Q, const float* __restrict__ Kg,
               const float* __restrict__ Vg, float* __restrict__ O)
{
    extern __shared__ __align__(16) float smem[];
    float* sQ  = smem;                 // 128 x 68
    float* sKh = sQ  + 128*68;         // 32 x 68
    float* sKl = sKh + 32*68;
    float* sVh = sKl + 32*68;          // 32 x 72
    float* sVl = sVh + 32*72;
    float* sPb = sVl + 32*72;          // 4 warps x (32 cols x 36)

    const int bh  = blockIdx.y;
    const int qt  = blockIdx.x;
    const int tid = threadIdx.x;
    const int wid = tid >> 5;
    const int lane = tid & 31;
    const int gid = lane >> 2;
    const int tig = lane & 3;
    const int m0  = wid * 32;
    float* sP = sPb + wid * (32*36);

    const float* Qbase = Q + ((size_t)bh * SEQ + qt * 128) * HDIM;
    const float* Kbase = Kg + (size_t)bh * SEQ * HDIM;
    const float* Vbase = Vg + (size_t)bh * SEQ * HDIM;

    // stage Q (128x64), scaled by 1/sqrt(D)
    {
        const float* qr = Qbase + (size_t)tid * HDIM;
#pragma unroll
        for (int i = 0; i < 16; i++) {
            float4 v = *(const float4*)(qr + i * 4);
            v.x *= 0.125f; v.y *= 0.125f; v.z *= 0.125f; v.w *= 0.125f;
            *(float4*)&QS(tid, i * 4) = v;
        }
    }
    __syncthreads();

    float o[2][8][4];
#pragma unroll
    for (int mt = 0; mt < 2; mt++)
#pragma unroll
        for (int nt = 0; nt < 8; nt++)
#pragma unroll
            for (int i = 0; i < 4; i++) o[mt][nt][i] = 0.f;
    float mrow[2][2] = {{-INFINITY,-INFINITY},{-INFINITY,-INFINITY}};
    float lrow[2][2] = {{0.f,0.f},{0.f,0.f}};

    const int qmax_warp = qt * 128 + m0 + 31;
    const int nch = 4 * qt + 4;

    for (int ch = 0; ch < nch; ch++) {
        // stage K,V chunk (32x64), pre-split
        {
            const int kr = tid >> 2, kc = (tid & 3) * 16;
            const float* kp = Kbase + (size_t)(ch * 32 + kr) * HDIM + kc;
            const float* vp = Vbase + (size_t)(ch * 32 + kr) * HDIM + kc;
#pragma unroll
            for (int i = 0; i < 4; i++) {
                float4 h, l;
                split4(*(const float4*)(kp + i * 4), h, l);
                *(float4*)&KHI(kr, kc + i * 4) = h;
                *(float4*)&KLO(kr, kc + i * 4) = l;
                split4(*(const float4*)(vp + i * 4), h, l);
                *(float4*)&VHI(kr, kc + i * 4) = h;
                *(float4*)&VLO(kr, kc + i * 4) = l;
            }
        }
        __syncthreads();

        if (ch * 32 <= qmax_warp) {
            // ---- S = Q K^T : 32 rows x 32 keys per warp ----
            float s[2][4][4];
#pragma unroll
            for (int mt = 0; mt < 2; mt++)
#pragma unroll
                for (int nt = 0; nt < 4; nt++)
#pragma unroll
                    for (int i = 0; i < 4; i++) s[mt][nt][i] = 0.f;

#pragma unroll
            for (int ks = 0; ks < 8; ks++) {
                uint32_t ahi[2][4], alo[2][4];
#pragma unroll
                for (int mt = 0; mt < 2; mt++) {
                    const int r0 = m0 + mt * 16;
                    float x0 = QS(r0 + gid,     ks*8 + tig);
                    float x1 = QS(r0 + gid + 8, ks*8 + tig);
                    float x2 = QS(r0 + gid,     ks*8 + tig + 4);
                    float x3 = QS(r0 + gid + 8, ks*8 + tig + 4);
                    tf32_split(x0, ahi[mt][0], alo[mt][0]);
                    tf32_split(x1, ahi[mt][1], alo[mt][1]);
                    tf32_split(x2, ahi[mt][2], alo[mt][2]);
                    tf32_split(x3, ahi[mt][3], alo[mt][3]);
                }
#pragma unroll
                for (int nt = 0; nt < 4; nt++) {
                    uint32_t bh[2], bl[2];
                    bh[0] = __float_as_uint(KHI(nt*8 + gid, ks*8 + tig));
                    bh[1] = __float_as_uint(KHI(nt*8 + gid, ks*8 + tig + 4));
                    bl[0] = __float_as_uint(KLO(nt*8 + gid, ks*8 + tig));
                    bl[1] = __float_as_uint(KLO(nt*8 + gid, ks*8 + tig + 4));
#pragma unroll
                    for (int mt = 0; mt < 2; mt++) {
                        mma_tf32(s[mt][nt], ahi[mt], bh);
                        mma_tf32(s[mt][nt], alo[mt], bh);
                        mma_tf32(s[mt][nt], ahi[mt], bl);
                    }
                }
            }

            // ---- register online softmax (per warp; rows owned exclusively) ----
#pragma unroll
            for (int mt = 0; mt < 2; mt++) {
#pragma unroll
                for (int half = 0; half < 2; half++) {
                    const int qrow = qt * 128 + m0 + mt * 16 + gid + half * 8;
                    const int cb   = ch * 32 + 2 * tig;
                    float mx = -INFINITY;
#pragma unroll
                    for (int nt = 0; nt < 4; nt++) {
#pragma unroll
                        for (int ii = 0; ii < 2; ii++) {
                            const int cc = cb + nt * 8 + ii;
                            if (cc <= qrow)
                                mx = fmaxf(mx, s[mt][nt][half * 2 + ii]);
                        }
                    }
                    mx = fmaxf(mx, __shfl_xor_sync(0xffffffffu, mx, 1));
                    mx = fmaxf(mx, __shfl_xor_sync(0xffffffffu, mx, 2));
                    const float mold = mrow[mt][half];
                    const float mnew = fmaxf(mold, mx);
                    const float msafe = (mnew == -INFINITY) ? 0.f : mnew;
                    const float corr  = (mold == -INFINITY) ? 0.f : __expf(mold - msafe);
                    float sum = 0.f;
#pragma unroll
                    for (int nt = 0; nt < 4; nt++) {
#pragma unroll
                        for (int ii = 0; ii < 2; ii++) {
                            const int cc = cb + nt * 8 + ii;
                            float p = (cc <= qrow) ? __expf(s[mt][nt][half*2+ii] - msafe) : 0.f;
                            s[mt][nt][half*2+ii] = p;
                            sum += p;
                        }
                    }
                    sum += __shfl_xor_sync(0xffffffffu, sum, 1);
                    sum += __shfl_xor_sync(0xffffffffu, sum, 2);
                    lrow[mt][half] = lrow[mt][half] * corr + sum;
                    mrow[mt][half] = mnew;
#pragma unroll
                    for (int nt = 0; nt < 8; nt++) {
                        o[mt][nt][half*2+0] *= corr;
                        o[mt][nt][half*2+1] *= corr;
                    }
                }
            }

            // ---- write P to per-warp buffer, layout [col][row] stride 36 ----
#pragma unroll
            for (int mt = 0; mt < 2; mt++) {
                const int rl = mt * 16 + gid;
#pragma unroll
                for (int nt = 0; nt < 4; nt++) {
                    const int cc = nt * 8 + 2 * tig;
                    SSW(cc,     rl)     = s[mt][nt][0];
                    SSW(cc + 1, rl)     = s[mt][nt][1];
                    SSW(cc,     rl + 8) = s[mt][nt][2];
                    SSW(cc + 1, rl + 8) = s[mt][nt][3];
                }
            }
            __syncwarp();

            // ---- O += P V ----
#pragma unroll
            for (int ks = 0; ks < 4; ks++) {
                uint32_t phi[2][4], plo[2][4];
#pragma unroll
                for (int mt = 0; mt < 2; mt++) {
                    const int rl = mt * 16 + gid;
                    float x0 = SSW(ks*8 + tig,     rl);
                    float x1 = SSW(ks*8 + tig,     rl + 8);
                    float x2 = SSW(ks*8 + tig + 4, rl);
                    float x3 = SSW(ks*8 + tig + 4, rl + 8);
                    tf32_split(x0, phi[mt][0], plo[mt][0]);
                    tf32_split(x1, phi[mt][1], plo[mt][1]);
                    tf32_split(x2, phi[mt][2], plo[mt][2]);
                    tf32_split(x3, phi[mt][3], plo[mt][3]);
                }
#pragma unroll
                for (int nt = 0; nt < 8; nt++) {
                    uint32_t vh[2], vl[2];
                    vh[0] = __float_as_uint(VHI(ks*8 + tig,     nt*8 + gid));
                    vh[1] = __float_as_uint(VHI(ks*8 + tig + 4, nt*8 + gid));
                    vl[0] = __float_as_uint(VLO(ks*8 + tig,     nt*8 + gid));
                    vl[1] = __float_as_uint(VLO(ks*8 + tig + 4, nt*8 + gid));
#pragma unroll
                    for (int mt = 0; mt < 2; mt++) {
                        mma_tf32(o[mt][nt], phi[mt], vh);
                        mma_tf32(o[mt][nt], plo[mt], vh);
                        mma_tf32(o[mt][nt], phi[mt], vl);
                    }
                }
            }
        }
        __syncthreads();
    }

    // epilogue
    const int b = bh / HEADS, h = bh % HEADS;
#pragma unroll
    for (int mt = 0; mt < 2; mt++) {
#pragma unroll
        for (int half = 0; half < 2; half++) {
            const float inv = 1.f / lrow[mt][half];
            const int sg = qt * 128 + m0 + mt * 16 + gid + half * 8;
            float* orow = O + ((size_t)(b * SEQ + sg)) * EMB + h * HDIM;
#pragma unroll
            for (int nt = 0; nt < 8; nt++) {
                const int cc = nt * 8 + 2 * tig;
                orow[cc]     = o[mt][nt][half*2+0] * inv;
                orow[cc + 1] = o[mt][nt][half*2+1] * inv;
            }
        }
    }
}

// ---------------------------------------------------------------------------
extern "C" void kernel_launch(void* const* d_in, const int* in_sizes, int n_in,
                              void* d_out, int out_size)
{
    const float* x  = (const float*)d_in[0];
    const float* Wq = (const float*)d_in[1];
    const float* bq = (const float*)d_in[2];
    const float* Wk = (const float*)d_in[3];
    const float* bk = (const float*)d_in[4];
    const float* Wv = (const float*)d_in[5];
    const float* bv = (const float*)d_in[6];
    const float* Wo = (const float*)d_in[7];
    const float* bo = (const float*)d_in[8];
    float* out = (float*)d_out;

    float *q_ptr, *k_ptr, *v_ptr, *ao_ptr;
    cudaGetSymbolAddress((void**)&q_ptr,  g_q);
    cudaGetSymbolAddress((void**)&k_ptr,  g_k);
    cudaGetSymbolAddress((void**)&v_ptr,  g_v);
    cudaGetSymbolAddress((void**)&ao_ptr, g_ao);

    const int attn_smem = ATTN_SMEM_FLOATS * 4;
    static int attn_attr_set = 0;
    if (!attn_attr_set) {
        cudaFuncSetAttribute(attn_tf32, cudaFuncAttributeMaxDynamicSharedMemorySize, attn_smem);
        attn_attr_set = 1;
    }

    dim3 gblk(256);
    dim3 ggrid(EMB / 128, MROWS / 128);   // (8, 64)

    gemm_tf32<<<ggrid, gblk>>>(x, Wq, bq, q_ptr, MROWS, EMB, EMB, 1);
    gemm_tf32<<<ggrid, gblk>>>(x, Wk, bk, k_ptr, MROWS, EMB, EMB, 1);
    gemm_tf32<<<ggrid, gblk>>>(x, Wv, bv, v_ptr, MROWS, EMB, EMB, 1);

    dim3 agrid(SEQ / 128, BATCH * HEADS);  // (16, 64)
    attn_tf32<<<agrid, 128, attn_smem>>>(q_ptr, k_ptr, v_ptr, ao_ptr);

    gemm_tf32<<<ggrid, gblk>>>(ao_ptr, Wo, bo, out, MROWS, EMB, EMB, 0);
}

// round 10
// speedup vs baseline: 1.7840x; 1.2452x over previous
#include <cuda_runtime.h>
#include <cstdint>
#include <cmath>

#define BATCH 4
#define SEQ   2048
#define EMB   1024
#define HEADS 16
#define HDIM  64
#define MROWS (BATCH*SEQ)   // 8192

// Scratch (no allocations allowed)
__device__ float g_q[BATCH*HEADS*SEQ*HDIM];
__device__ float g_k[BATCH*HEADS*SEQ*HDIM];
__device__ float g_v[BATCH*HEADS*SEQ*HDIM];
__device__ float g_ao[BATCH*SEQ*EMB];

// ---------------------------------------------------------------------------
// helpers
// ---------------------------------------------------------------------------
__device__ __forceinline__ uint32_t tf32_rna(float x) {
    uint32_t r;
    asm("cvt.rna.tf32.f32 %0, %1;" : "=r"(r) : "f"(x));
    return r;
}
__device__ __forceinline__ void tf32_split(float x, uint32_t& hi, uint32_t& lo) {
    hi = tf32_rna(x);
    lo = tf32_rna(x - __uint_as_float(hi));
}
__device__ __forceinline__ void split4(const float4 v, float4& hi, float4& lo) {
    uint32_t h, l;
    tf32_split(v.x, h, l); hi.x = __uint_as_float(h); lo.x = __uint_as_float(l);
    tf32_split(v.y, h, l); hi.y = __uint_as_float(h); lo.y = __uint_as_float(l);
    tf32_split(v.z, h, l); hi.z = __uint_as_float(h); lo.z = __uint_as_float(l);
    tf32_split(v.w, h, l); hi.w = __uint_as_float(h); lo.w = __uint_as_float(l);
}
__device__ __forceinline__ float4 cvt4(float4 v) {
    v.x = __uint_as_float(tf32_rna(v.x));
    v.y = __uint_as_float(tf32_rna(v.y));
    v.z = __uint_as_float(tf32_rna(v.z));
    v.w = __uint_as_float(tf32_rna(v.w));
    return v;
}
__device__ __forceinline__ void mma_tf32(float* c, const uint32_t* a, const uint32_t* b) {
    asm volatile(
        "mma.sync.aligned.m16n8k8.row.col.f32.tf32.tf32.f32 "
        "{%0,%1,%2,%3}, {%4,%5,%6,%7}, {%8,%9}, {%0,%1,%2,%3};"
        : "+f"(c[0]), "+f"(c[1]), "+f"(c[2]), "+f"(c[3])
        : "r"(a[0]), "r"(a[1]), "r"(a[2]), "r"(a[3]), "r"(b[0]), "r"(b[1]));
}

// ---------------------------------------------------------------------------
// 3xTF32 GEMM body, double-buffered pre-split SMEM.
// C = A[8192,1024] @ B[1024,1024] + bias. Tile 128x128x16, 256 thr, 8 warps.
// ---------------------------------------------------------------------------
#define GSTG 9472   // floats per stage: A(2*128*20=5120) + B(2*16*136=4352)
#define SAh(st,r,c) sm[(st)*GSTG          + (r)*20  + (c)]
#define SAl(st,r,c) sm[(st)*GSTG + 2560   + (r)*20  + (c)]
#define SBh(st,r,c) sm[(st)*GSTG + 5120   + (r)*136 + (c)]
#define SBl(st,r,c) sm[(st)*GSTG + 7296   + (r)*136 + (c)]
#define GEMM_SMEM_BYTES (2*GSTG*4)

__device__ __forceinline__ void gemm_body(
    const float* __restrict__ A, const float* __restrict__ Bm,
    const float* __restrict__ bias, float* __restrict__ C,
    int headsplit, float* sm)
{
    const int K = EMB, N = EMB;
    const int tid  = threadIdx.x;
    const int wid  = tid >> 5;
    const int lane = tid & 31;
    const int gid  = lane >> 2;
    const int tig  = lane & 3;
    const int wm   = wid >> 1;
    const int wn   = wid & 1;
    const int row0 = blockIdx.y * 128;
    const int col0 = blockIdx.x * 128;

    float c[2][8][4];
#pragma unroll
    for (int mt = 0; mt < 2; mt++)
#pragma unroll
        for (int nt = 0; nt < 8; nt++)
#pragma unroll
            for (int i = 0; i < 4; i++) c[mt][nt][i] = 0.f;

    const int ar = tid >> 1, ac = (tid & 1) * 8;
    const int br = tid >> 4, bc = (tid & 15) * 8;

    const float* Abase = A + (size_t)(row0 + ar) * K + ac;
    const float* Bbase = Bm + (size_t)br * N + col0 + bc;

    float4 aR0 = *(const float4*)(Abase);
    float4 aR1 = *(const float4*)(Abase + 4);
    float4 bR0 = *(const float4*)(Bbase);
    float4 bR1 = *(const float4*)(Bbase + 4);

    // stage 0
    {
        float4 h, l;
        split4(aR0, h, l); *(float4*)&SAh(0,ar,ac)   = h; *(float4*)&SAl(0,ar,ac)   = l;
        split4(aR1, h, l); *(float4*)&SAh(0,ar,ac+4) = h; *(float4*)&SAl(0,ar,ac+4) = l;
        split4(bR0, h, l); *(float4*)&SBh(0,br,bc)   = h; *(float4*)&SBl(0,br,bc)   = l;
        split4(bR1, h, l); *(float4*)&SBh(0,br,bc+4) = h; *(float4*)&SBl(0,br,bc+4) = l;
    }
    __syncthreads();

    int cur = 0;
    for (int k0 = 0; k0 < K; k0 += 16) {
        const bool more = (k0 + 16 < K);
        if (more) {
            aR0 = *(const float4*)(Abase + k0 + 16);
            aR1 = *(const float4*)(Abase + k0 + 20);
            bR0 = *(const float4*)(Bbase + (size_t)(k0 + 16) * N);
            bR1 = *(const float4*)(Bbase + (size_t)(k0 + 16) * N + 4);
        }

#pragma unroll
        for (int ks = 0; ks < 2; ks++) {
            uint32_t ahi[2][4], alo[2][4];
#pragma unroll
            for (int mt = 0; mt < 2; mt++) {
                const int m0 = wm * 32 + mt * 16;
                ahi[mt][0] = __float_as_uint(SAh(cur, m0 + gid,     ks*8 + tig));
                ahi[mt][1] = __float_as_uint(SAh(cur, m0 + gid + 8, ks*8 + tig));
                ahi[mt][2] = __float_as_uint(SAh(cur, m0 + gid,     ks*8 + tig + 4));
                ahi[mt][3] = __float_as_uint(SAh(cur, m0 + gid + 8, ks*8 + tig + 4));
                alo[mt][0] = __float_as_uint(SAl(cur, m0 + gid,     ks*8 + tig));
                alo[mt][1] = __float_as_uint(SAl(cur, m0 + gid + 8, ks*8 + tig));
                alo[mt][2] = __float_as_uint(SAl(cur, m0 + gid,     ks*8 + tig + 4));
                alo[mt][3] = __float_as_uint(SAl(cur, m0 + gid + 8, ks*8 + tig + 4));
            }
#pragma unroll
            for (int nt = 0; nt < 8; nt++) {
                const int n0 = wn * 64 + nt * 8;
                uint32_t bh[2], bl[2];
                bh[0] = __float_as_uint(SBh(cur, ks*8 + tig,     n0 + gid));
                bh[1] = __float_as_uint(SBh(cur, ks*8 + tig + 4, n0 + gid));
                bl[0] = __float_as_uint(SBl(cur, ks*8 + tig,     n0 + gid));
                bl[1] = __float_as_uint(SBl(cur, ks*8 + tig + 4, n0 + gid));
#pragma unroll
                for (int mt = 0; mt < 2; mt++) {
                    mma_tf32(c[mt][nt], ahi[mt], bh);
                    mma_tf32(c[mt][nt], alo[mt], bh);
                    mma_tf32(c[mt][nt], ahi[mt], bl);
                }
            }
        }

        if (more) {
            const int nxt = cur ^ 1;
            float4 h, l;
            split4(aR0, h, l); *(float4*)&SAh(nxt,ar,ac)   = h; *(float4*)&SAl(nxt,ar,ac)   = l;
            split4(aR1, h, l); *(float4*)&SAh(nxt,ar,ac+4) = h; *(float4*)&SAl(nxt,ar,ac+4) = l;
            split4(bR0, h, l); *(float4*)&SBh(nxt,br,bc)   = h; *(float4*)&SBl(nxt,br,bc)   = l;
            split4(bR1, h, l); *(float4*)&SBh(nxt,br,bc+4) = h; *(float4*)&SBl(nxt,br,bc+4) = l;
            __syncthreads();
            cur = nxt;
        }
    }

#pragma unroll
    for (int mt = 0; mt < 2; mt++) {
        const int m_lo = row0 + wm * 32 + mt * 16 + gid;
        const int m_hi = m_lo + 8;
#pragma unroll
        for (int nt = 0; nt < 8; nt++) {
            const int n = col0 + wn * 64 + nt * 8 + 2 * tig;
            const float b0 = bias[n], b1 = bias[n + 1];
            float v00 = c[mt][nt][0] + b0, v01 = c[mt][nt][1] + b1;
            float v10 = c[mt][nt][2] + b0, v11 = c[mt][nt][3] + b1;
            if (headsplit) {
                const int b_lo = m_lo / SEQ, s_lo = m_lo % SEQ;
                const int b_hi = m_hi / SEQ, s_hi = m_hi % SEQ;
                const int h = n / HDIM, d = n % HDIM;
                C[(((size_t)(b_lo*HEADS + h))*SEQ + s_lo)*HDIM + d    ] = v00;
                C[(((size_t)(b_lo*HEADS + h))*SEQ + s_lo)*HDIM + d + 1] = v01;
                C[(((size_t)(b_hi*HEADS + h))*SEQ + s_hi)*HDIM + d    ] = v10;
                C[(((size_t)(b_hi*HEADS + h))*SEQ + s_hi)*HDIM + d + 1] = v11;
            } else {
                C[(size_t)m_lo * N + n    ] = v00;
                C[(size_t)m_lo * N + n + 1] = v01;
                C[(size_t)m_hi * N + n    ] = v10;
                C[(size_t)m_hi * N + n + 1] = v11;
            }
        }
    }
}

// merged Q/K/V projections: blockIdx.z selects weight/bias/output
__global__ __launch_bounds__(256)
void gemm_proj(const float* __restrict__ A,
               const float* __restrict__ W0, const float* __restrict__ W1,
               const float* __restrict__ W2,
               const float* __restrict__ b0, const float* __restrict__ b1,
               const float* __restrict__ b2,
               float* __restrict__ C0, float* __restrict__ C1, float* __restrict__ C2)
{
    extern __shared__ __align__(16) float sm[];
    const int z = blockIdx.z;
    const float* W = (z == 0) ? W0 : (z == 1) ? W1 : W2;
    const float* b = (z == 0) ? b0 : (z == 1) ? b1 : b2;
    float*       C = (z == 0) ? C0 : (z == 1) ? C1 : C2;
    gemm_body(A, W, b, C, 1, sm);
}

__global__ __launch_bounds__(256)
void gemm_out(const float* __restrict__ A, const float* __restrict__ W,
              const float* __restrict__ b, float* __restrict__ C)
{
    extern __shared__ __align__(16) float sm[];
    gemm_body(A, W, b, C, 0, sm);
}

// ---------------------------------------------------------------------------
// Causal flash attention, single-pass TF32.
// Block: 128 q-rows, 128 threads, 4 warps; warp owns 32 rows (2 m-tiles).
// Key chunks of 32. All operands pre-cvt'd to tf32 in SMEM.
// ---------------------------------------------------------------------------
#define QS(r,c)    sQ[(r)*68 + (c)]
#define KS_(r,c)   sK[(r)*68 + (c)]
#define VS_(r,c)   sV[(r)*72 + (c)]
#define SSW(cc,rr) sP[(cc)*40 + (rr)]

#define ATTN_SMEM_FLOATS (128*68 + 32*68 + 32*72 + 4*32*40)

__global__ __launch_bounds__(128)
void attn_tf32(const float* __restrict__ Q, const float* __restrict__ Kg,
               const float* __restrict__ Vg, float* __restrict__ O)
{
    extern __shared__ __align__(16) float smem[];
    float* sQ  = smem;                 // 128 x 68
    float* sK  = sQ + 128*68;          // 32 x 68
    float* sV  = sK + 32*68;           // 32 x 72
    float* sPb = sV + 32*72;           // 4 warps x (32 cols x 40)

    const int bh  = blockIdx.y;
    const int qt  = blockIdx.x;
    const int tid = threadIdx.x;
    const int wid = tid >> 5;
    const int lane = tid & 31;
    const int gid = lane >> 2;
    const int tig = lane & 3;
    const int m0  = wid * 32;
    float* sP = sPb + wid * (32*40);

    const float* Qbase = Q + ((size_t)bh * SEQ + qt * 128) * HDIM;
    const float* Kbase = Kg + (size_t)bh * SEQ * HDIM;
    const float* Vbase = Vg + (size_t)bh * SEQ * HDIM;

    // stage Q (128x64), scaled by 1/sqrt(D), cvt to tf32
    {
        const float* qr = Qbase + (size_t)tid * HDIM;
#pragma unroll
        for (int i = 0; i < 16; i++) {
            float4 v = *(const float4*)(qr + i * 4);
            v.x *= 0.125f; v.y *= 0.125f; v.z *= 0.125f; v.w *= 0.125f;
            *(float4*)&QS(tid, i * 4) = cvt4(v);
        }
    }
    __syncthreads();

    float o[2][8][4];
#pragma unroll
    for (int mt = 0; mt < 2; mt++)
#pragma unroll
        for (int nt = 0; nt < 8; nt++)
#pragma unroll
            for (int i = 0; i < 4; i++) o[mt][nt][i] = 0.f;
    float mrow[2][2] = {{-INFINITY,-INFINITY},{-INFINITY,-INFINITY}};
    float lrow[2][2] = {{0.f,0.f},{0.f,0.f}};

    const int qmax_warp = qt * 128 + m0 + 31;
    const int nch = 4 * qt + 4;

    for (int ch = 0; ch < nch; ch++) {
        // stage K,V chunk (32x64), cvt to tf32
        {
            const int kr = tid >> 2, kc = (tid & 3) * 16;
            const float* kp = Kbase + (size_t)(ch * 32 + kr) * HDIM + kc;
            const float* vp = Vbase + (size_t)(ch * 32 + kr) * HDIM + kc;
#pragma unroll
            for (int i = 0; i < 4; i++) {
                *(float4*)&KS_(kr, kc + i * 4) = cvt4(*(const float4*)(kp + i * 4));
                *(float4*)&VS_(kr, kc + i * 4) = cvt4(*(const float4*)(vp + i * 4));
            }
        }
        __syncthreads();

        if (ch * 32 <= qmax_warp) {
            // ---- S = Q K^T : 32 rows x 32 keys per warp ----
            float s[2][4][4];
#pragma unroll
            for (int mt = 0; mt < 2; mt++)
#pragma unroll
                for (int nt = 0; nt < 4; nt++)
#pragma unroll
                    for (int i = 0; i < 4; i++) s[mt][nt][i] = 0.f;

#pragma unroll
            for (int ks = 0; ks < 8; ks++) {
                uint32_t a[2][4];
#pragma unroll
                for (int mt = 0; mt < 2; mt++) {
                    const int r0 = m0 + mt * 16;
                    a[mt][0] = __float_as_uint(QS(r0 + gid,     ks*8 + tig));
                    a[mt][1] = __float_as_uint(QS(r0 + gid + 8, ks*8 + tig));
                    a[mt][2] = __float_as_uint(QS(r0 + gid,     ks*8 + tig + 4));
                    a[mt][3] = __float_as_uint(QS(r0 + gid + 8, ks*8 + tig + 4));
                }
#pragma unroll
                for (int nt = 0; nt < 4; nt++) {
                    uint32_t b[2];
                    b[0] = __float_as_uint(KS_(nt*8 + gid, ks*8 + tig));
                    b[1] = __float_as_uint(KS_(nt*8 + gid, ks*8 + tig + 4));
                    mma_tf32(s[0][nt], a[0], b);
                    mma_tf32(s[1][nt], a[1], b);
                }
            }

            // ---- register online softmax ----
#pragma unroll
            for (int mt = 0; mt < 2; mt++) {
#pragma unroll
                for (int half = 0; half < 2; half++) {
                    const int qrow = qt * 128 + m0 + mt * 16 + gid + half * 8;
                    const int cb   = ch * 32 + 2 * tig;
                    float mx = -INFINITY;
#pragma unroll
                    for (int nt = 0; nt < 4; nt++) {
#pragma unroll
                        for (int ii = 0; ii < 2; ii++) {
                            const int cc = cb + nt * 8 + ii;
                            if (cc <= qrow)
                                mx = fmaxf(mx, s[mt][nt][half * 2 + ii]);
                        }
                    }
                    mx = fmaxf(mx, __shfl_xor_sync(0xffffffffu, mx, 1));
                    mx = fmaxf(mx, __shfl_xor_sync(0xffffffffu, mx, 2));
                    const float mold = mrow[mt][half];
                    const float mnew = fmaxf(mold, mx);
                    const float msafe = (mnew == -INFINITY) ? 0.f : mnew;
                    const float corr  = (mold == -INFINITY) ? 0.f : __expf(mold - msafe);
                    float sum = 0.f;
#pragma unroll
                    for (int nt = 0; nt < 4; nt++) {
#pragma unroll
                        for (int ii = 0; ii < 2; ii++) {
                            const int cc = cb + nt * 8 + ii;
                            float p = (cc <= qrow) ? __expf(s[mt][nt][half*2+ii] - msafe) : 0.f;
                            s[mt][nt][half*2+ii] = p;
                            sum += p;
                        }
                    }
                    sum += __shfl_xor_sync(0xffffffffu, sum, 1);
                    sum += __shfl_xor_sync(0xffffffffu, sum, 2);
                    lrow[mt][half] = lrow[mt][half] * corr + sum;
                    mrow[mt][half] = mnew;
#pragma unroll
                    for (int nt = 0; nt < 8; nt++) {
                        o[mt][nt][half*2+0] *= corr;
                        o[mt][nt][half*2+1] *= corr;
                    }
                }
            }

            // ---- write P (tf32-cvt'd) to per-warp buffer [col][row] stride 40 ----
#pragma unroll
            for (int mt = 0; mt < 2; mt++) {
                const int rl = mt * 16 + gid;
#pragma unroll
                for (int nt = 0; nt < 4; nt++) {
                    const int cc = nt * 8 + 2 * tig;
                    SSW(cc,     rl)     = __uint_as_float(tf32_rna(s[mt][nt][0]));
                    SSW(cc + 1, rl)     = __uint_as_float(tf32_rna(s[mt][nt][1]));
                    SSW(cc,     rl + 8) = __uint_as_float(tf32_rna(s[mt][nt][2]));
                    SSW(cc + 1, rl + 8) = __uint_as_float(tf32_rna(s[mt][nt][3]));
                }
            }
            __syncwarp();

            // ---- O += P V ----
#pragma unroll
            for (int ks = 0; ks < 4; ks++) {
                uint32_t p[2][4];
#pragma unroll
                for (int mt = 0; mt < 2; mt++) {
                    const int rl = mt * 16 + gid;
                    p[mt][0] = __float_as_uint(SSW(ks*8 + tig,     rl));
                    p[mt][1] = __float_as_uint(SSW(ks*8 + tig,     rl + 8));
                    p[mt][2] = __float_as_uint(SSW(ks*8 + tig + 4, rl));
                    p[mt][3] = __float_as_uint(SSW(ks*8 + tig + 4, rl + 8));
                }
#pragma unroll
                for (int nt = 0; nt < 8; nt++) {
                    uint32_t v[2];
                    v[0] = __float_as_uint(VS_(ks*8 + tig,     nt*8 + gid));
                    v[1] = __float_as_uint(VS_(ks*8 + tig + 4, nt*8 + gid));
                    mma_tf32(o[0][nt], p[0], v);
                    mma_tf32(o[1][nt], p[1], v);
                }
            }
        }
        __syncthreads();
    }

    // epilogue: normalize and store to [b][s][h*64+d]
    const int b = bh / HEADS, h = bh % HEADS;
#pragma unroll
    for (int mt = 0; mt < 2; mt++) {
#pragma unroll
        for (int half = 0; half < 2; half++) {
            const float inv = 1.f / lrow[mt][half];
            const int sg = qt * 128 + m0 + mt * 16 + gid + half * 8;
            float* orow = O + ((size_t)(b * SEQ + sg)) * EMB + h * HDIM;
#pragma unroll
            for (int nt = 0; nt < 8; nt++) {
                const int cc = nt * 8 + 2 * tig;
                orow[cc]     = o[mt][nt][half*2+0] * inv;
                orow[cc + 1] = o[mt][nt][half*2+1] * inv;
            }
        }
    }
}

// ---------------------------------------------------------------------------
extern "C" void kernel_launch(void* const* d_in, const int* in_sizes, int n_in,
                              void* d_out, int out_size)
{
    const float* x  = (const float*)d_in[0];
    const float* Wq = (const float*)d_in[1];
    const float* bq = (const float*)d_in[2];
    const float* Wk = (const float*)d_in[3];
    const float* bk = (const float*)d_in[4];
    const float* Wv = (const float*)d_in[5];
    const float* bv = (const float*)d_in[6];
    const float* Wo = (const float*)d_in[7];
    const float* bo = (const float*)d_in[8];
    float* out = (float*)d_out;

    float *q_ptr, *k_ptr, *v_ptr, *ao_ptr;
    cudaGetSymbolAddress((void**)&q_ptr,  g_q);
    cudaGetSymbolAddress((void**)&k_ptr,  g_k);
    cudaGetSymbolAddress((void**)&v_ptr,  g_v);
    cudaGetSymbolAddress((void**)&ao_ptr, g_ao);

    const int attn_smem = ATTN_SMEM_FLOATS * 4;
    static int attr_set = 0;
    if (!attr_set) {
        cudaFuncSetAttribute(attn_tf32,  cudaFuncAttributeMaxDynamicSharedMemorySize, attn_smem);
        cudaFuncSetAttribute(gemm_proj,  cudaFuncAttributeMaxDynamicSharedMemorySize, GEMM_SMEM_BYTES);
        cudaFuncSetAttribute(gemm_out,   cudaFuncAttributeMaxDynamicSharedMemorySize, GEMM_SMEM_BYTES);
        attr_set = 1;
    }

    dim3 gblk(256);
    dim3 pgrid(EMB / 128, MROWS / 128, 3);   // (8, 64, 3)
    gemm_proj<<<pgrid, gblk, GEMM_SMEM_BYTES>>>(x, Wq, Wk, Wv, bq, bk, bv,
                                                q_ptr, k_ptr, v_ptr);

    dim3 agrid(SEQ / 128, BATCH * HEADS);    // (16, 64)
    attn_tf32<<<agrid, 128, attn_smem>>>(q_ptr, k_ptr, v_ptr, ao_ptr);

    dim3 ogrid(EMB / 128, MROWS / 128, 1);   // (8, 64)
    gemm_out<<<ogrid, gblk, GEMM_SMEM_BYTES>>>(ao_ptr, Wo, bo, out);
}

// round 12
// speedup vs baseline: 2.6881x; 1.5068x over previous
#include <cuda_runtime.h>
#include <cuda_bf16.h>
#include <cstdint>
#include <cmath>

#define BATCH 4
#define SEQ   2048
#define EMB   1024
#define HEADS 16
#define HDIM  64
#define MROWS (BATCH*SEQ)   // 8192

// Scratch (no allocations allowed)
__device__ float g_q[BATCH*HEADS*SEQ*HDIM];
__device__ float g_k[BATCH*HEADS*SEQ*HDIM];
__device__ float g_v[BATCH*HEADS*SEQ*HDIM];
__device__ float g_ao[BATCH*SEQ*EMB];

// ---------------------------------------------------------------------------
// helpers
// ---------------------------------------------------------------------------
__device__ __forceinline__ uint32_t tf32_rna(float x) {
    uint32_t r;
    asm("cvt.rna.tf32.f32 %0, %1;" : "=r"(r) : "f"(x));
    return r;
}
__device__ __forceinline__ float4 cvt4(float4 v) {
    v.x = __uint_as_float(tf32_rna(v.x));
    v.y = __uint_as_float(tf32_rna(v.y));
    v.z = __uint_as_float(tf32_rna(v.z));
    v.w = __uint_as_float(tf32_rna(v.w));
    return v;
}
__device__ __forceinline__ void mma_tf32(float* c, const uint32_t* a, const uint32_t* b) {
    asm volatile(
        "mma.sync.aligned.m16n8k8.row.col.f32.tf32.tf32.f32 "
        "{%0,%1,%2,%3}, {%4,%5,%6,%7}, {%8,%9}, {%0,%1,%2,%3};"
        : "+f"(c[0]), "+f"(c[1]), "+f"(c[2]), "+f"(c[3])
        : "r"(a[0]), "r"(a[1]), "r"(a[2]), "r"(a[3]), "r"(b[0]), "r"(b[1]));
}
__device__ __forceinline__ void mma_bf16(float* c, const uint32_t* a, const uint32_t* b) {
    asm volatile(
        "mma.sync.aligned.m16n8k16.row.col.f32.bf16.bf16.f32 "
        "{%0,%1,%2,%3}, {%4,%5,%6,%7}, {%8,%9}, {%0,%1,%2,%3};"
        : "+f"(c[0]), "+f"(c[1]), "+f"(c[2]), "+f"(c[3])
        : "r"(a[0]), "r"(a[1]), "r"(a[2]), "r"(a[3]), "r"(b[0]), "r"(b[1]));
}
// split x0,x1 into bf16 hi/lo pairs packed as uint32 (x0 in low half, x1 in high)
__device__ __forceinline__ void bf16split2(float x0, float x1, uint32_t& hi, uint32_t& lo) {
    __nv_bfloat16 h0 = __float2bfloat16_rn(x0);
    __nv_bfloat16 h1 = __float2bfloat16_rn(x1);
    float r0 = x0 - __bfloat162float(h0);
    float r1 = x1 - __bfloat162float(h1);
    __nv_bfloat16 l0 = __float2bfloat16_rn(r0);
    __nv_bfloat16 l1 = __float2bfloat16_rn(r1);
    hi = ((uint32_t)__bfloat16_as_ushort(h1) << 16) | (uint32_t)__bfloat16_as_ushort(h0);
    lo = ((uint32_t)__bfloat16_as_ushort(l1) << 16) | (uint32_t)__bfloat16_as_ushort(l0);
}

// ---------------------------------------------------------------------------
// 3xBF16 GEMM body, double-buffered packed SMEM.
// C = A[8192,1024] @ B[1024,1024] + bias. Tile 128x128x16, 256 thr, 8 warps.
// SMEM (uint32): A [row 128][k-pair 8] stride 12 (hi & lo),
//                B [k-pair 8][col 128] stride 136 (hi & lo).
// ---------------------------------------------------------------------------
#define GSTG 5248   // uint32 per stage: 2*128*12 + 2*8*136
#define SAh(st,r,p) smu[(st)*GSTG          + (r)*12  + (p)]
#define SAl(st,r,p) smu[(st)*GSTG + 1536   + (r)*12  + (p)]
#define SBh(st,p,c) smu[(st)*GSTG + 3072   + (p)*136 + (c)]
#define SBl(st,p,c) smu[(st)*GSTG + 4160   + (p)*136 + (c)]
#define GEMM_SMEM_BYTES (2*GSTG*4)

__device__ __forceinline__ void gemm_body(
    const float* __restrict__ A, const float* __restrict__ Bm,
    const float* __restrict__ bias, float* __restrict__ C,
    int headsplit, uint32_t* smu)
{
    const int K = EMB, N = EMB;
    const int tid  = threadIdx.x;
    const int wid  = tid >> 5;
    const int lane = tid & 31;
    const int gid  = lane >> 2;
    const int tig  = lane & 3;
    const int wm   = wid >> 1;
    const int wn   = wid & 1;
    const int row0 = blockIdx.y * 128;
    const int col0 = blockIdx.x * 128;

    float c[2][8][4];
#pragma unroll
    for (int mt = 0; mt < 2; mt++)
#pragma unroll
        for (int nt = 0; nt < 8; nt++)
#pragma unroll
            for (int i = 0; i < 4; i++) c[mt][nt][i] = 0.f;

    // A staging: thread -> row ar, k-cols ac..ac+7 (pairs p0..p0+3)
    const int ar = tid >> 1, ac = (tid & 1) * 8, ap0 = (tid & 1) * 4;
    // B staging: thread -> k-rows 2br,2br+1, cols bc..bc+3 (pair br)
    const int br = tid >> 5, bc = (tid & 31) * 4;

    const float* Abase  = A + (size_t)(row0 + ar) * K + ac;
    const float* Bbase0 = Bm + (size_t)(2*br    ) * N + col0 + bc;
    const float* Bbase1 = Bm + (size_t)(2*br + 1) * N + col0 + bc;

    float4 aR0 = *(const float4*)(Abase);
    float4 aR1 = *(const float4*)(Abase + 4);
    float4 bRa = *(const float4*)(Bbase0);
    float4 bRb = *(const float4*)(Bbase1);

    // stage 0
    {
        uint32_t h[4], l[4];
        bf16split2(aR0.x, aR0.y, h[0], l[0]);
        bf16split2(aR0.z, aR0.w, h[1], l[1]);
        bf16split2(aR1.x, aR1.y, h[2], l[2]);
        bf16split2(aR1.z, aR1.w, h[3], l[3]);
        *(uint4*)&SAh(0, ar, ap0) = make_uint4(h[0], h[1], h[2], h[3]);
        *(uint4*)&SAl(0, ar, ap0) = make_uint4(l[0], l[1], l[2], l[3]);
        bf16split2(bRa.x, bRb.x, h[0], l[0]);
        bf16split2(bRa.y, bRb.y, h[1], l[1]);
        bf16split2(bRa.z, bRb.z, h[2], l[2]);
        bf16split2(bRa.w, bRb.w, h[3], l[3]);
        *(uint4*)&SBh(0, br, bc) = make_uint4(h[0], h[1], h[2], h[3]);
        *(uint4*)&SBl(0, br, bc) = make_uint4(l[0], l[1], l[2], l[3]);
    }
    __syncthreads();

    int cur = 0;
    for (int k0 = 0; k0 < K; k0 += 16) {
        const bool more = (k0 + 16 < K);
        if (more) {
            aR0 = *(const float4*)(Abase + k0 + 16);
            aR1 = *(const float4*)(Abase + k0 + 20);
            bRa = *(const float4*)(Bbase0 + (size_t)(k0 + 16) * N);
            bRb = *(const float4*)(Bbase1 + (size_t)(k0 + 16) * N);
        }

        uint32_t ahi[2][4], alo[2][4];
#pragma unroll
        for (int mt = 0; mt < 2; mt++) {
            const int m0 = wm * 32 + mt * 16;
            ahi[mt][0] = SAh(cur, m0 + gid,     tig);
            ahi[mt][1] = SAh(cur, m0 + gid + 8, tig);
            ahi[mt][2] = SAh(cur, m0 + gid,     tig + 4);
            ahi[mt][3] = SAh(cur, m0 + gid + 8, tig + 4);
            alo[mt][0] = SAl(cur, m0 + gid,     tig);
            alo[mt][1] = SAl(cur, m0 + gid + 8, tig);
            alo[mt][2] = SAl(cur, m0 + gid,     tig + 4);
            alo[mt][3] = SAl(cur, m0 + gid + 8, tig + 4);
        }
#pragma unroll
        for (int nt = 0; nt < 8; nt++) {
            const int n0 = wn * 64 + nt * 8;
            uint32_t bh[2], bl[2];
            bh[0] = SBh(cur, tig,     n0 + gid);
            bh[1] = SBh(cur, tig + 4, n0 + gid);
            bl[0] = SBl(cur, tig,     n0 + gid);
            bl[1] = SBl(cur, tig + 4, n0 + gid);
#pragma unroll
            for (int mt = 0; mt < 2; mt++) {
                mma_bf16(c[mt][nt], ahi[mt], bh);
                mma_bf16(c[mt][nt], alo[mt], bh);
                mma_bf16(c[mt][nt], ahi[mt], bl);
            }
        }

        if (more) {
            const int nxt = cur ^ 1;
            uint32_t h[4], l[4];
            bf16split2(aR0.x, aR0.y, h[0], l[0]);
            bf16split2(aR0.z, aR0.w, h[1], l[1]);
            bf16split2(aR1.x, aR1.y, h[2], l[2]);
            bf16split2(aR1.z, aR1.w, h[3], l[3]);
            *(uint4*)&SAh(nxt, ar, ap0) = make_uint4(h[0], h[1], h[2], h[3]);
            *(uint4*)&SAl(nxt, ar, ap0) = make_uint4(l[0], l[1], l[2], l[3]);
            bf16split2(bRa.x, bRb.x, h[0], l[0]);
            bf16split2(bRa.y, bRb.y, h[1], l[1]);
            bf16split2(bRa.z, bRb.z, h[2], l[2]);
            bf16split2(bRa.w, bRb.w, h[3], l[3]);
            *(uint4*)&SBh(nxt, br, bc) = make_uint4(h[0], h[1], h[2], h[3]);
            *(uint4*)&SBl(nxt, br, bc) = make_uint4(l[0], l[1], l[2], l[3]);
            __syncthreads();
            cur = nxt;
        }
    }

#pragma unroll
    for (int mt = 0; mt < 2; mt++) {
        const int m_lo = row0 + wm * 32 + mt * 16 + gid;
        const int m_hi = m_lo + 8;
#pragma unroll
        for (int nt = 0; nt < 8; nt++) {
            const int n = col0 + wn * 64 + nt * 8 + 2 * tig;
            const float b0 = bias[n], b1 = bias[n + 1];
            float v00 = c[mt][nt][0] + b0, v01 = c[mt][nt][1] + b1;
            float v10 = c[mt][nt][2] + b0, v11 = c[mt][nt][3] + b1;
            if (headsplit) {
                const int b_lo = m_lo / SEQ, s_lo = m_lo % SEQ;
                const int b_hi = m_hi / SEQ, s_hi = m_hi % SEQ;
                const int h = n / HDIM, d = n % HDIM;
                C[(((size_t)(b_lo*HEADS + h))*SEQ + s_lo)*HDIM + d    ] = v00;
                C[(((size_t)(b_lo*HEADS + h))*SEQ + s_lo)*HDIM + d + 1] = v01;
                C[(((size_t)(b_hi*HEADS + h))*SEQ + s_hi)*HDIM + d    ] = v10;
                C[(((size_t)(b_hi*HEADS + h))*SEQ + s_hi)*HDIM + d + 1] = v11;
            } else {
                C[(size_t)m_lo * N + n    ] = v00;
                C[(size_t)m_lo * N + n + 1] = v01;
                C[(size_t)m_hi * N + n    ] = v10;
                C[(size_t)m_hi * N + n + 1] = v11;
            }
        }
    }
}

// merged Q/K/V projections: blockIdx.z selects weight/bias/output
__global__ __launch_bounds__(256)
void gemm_proj(const float* __restrict__ A,
               const float* __restrict__ W0, const float* __restrict__ W1,
               const float* __restrict__ W2,
               const float* __restrict__ b0, const float* __restrict__ b1,
               const float* __restrict__ b2,
               float* __restrict__ C0, float* __restrict__ C1, float* __restrict__ C2)
{
    extern __shared__ __align__(16) uint32_t smu[];
    const int z = blockIdx.z;
    const float* W = (z == 0) ? W0 : (z == 1) ? W1 : W2;
    const float* b = (z == 0) ? b0 : (z == 1) ? b1 : b2;
    float*       C = (z == 0) ? C0 : (z == 1) ? C1 : C2;
    gemm_body(A, W, b, C, 1, smu);
}

__global__ __launch_bounds__(256)
void gemm_out(const float* __restrict__ A, const float* __restrict__ W,
              const float* __restrict__ b, float* __restrict__ C)
{
    extern __shared__ __align__(16) uint32_t smu[];
    gemm_body(A, W, b, C, 0, smu);
}

// ---------------------------------------------------------------------------
// Causal flash attention, single-pass TF32.
// Block: 128 q-rows, 128 threads, 4 warps; warp owns 32 rows (2 m-tiles).
// ---------------------------------------------------------------------------
#define QS(r,c)    sQ[(r)*68 + (c)]
#define KS_(r,c)   sK[(r)*68 + (c)]
#define VS_(r,c)   sV[(r)*72 + (c)]
#define SSW(cc,rr) sP[(cc)*40 + (rr)]

#define ATTN_SMEM_FLOATS (128*68 + 32*68 + 32*72 + 4*32*40)

__global__ __launch_bounds__(128)
void attn_tf32(const float* __restrict__ Q, const float* __restrict__ Kg,
               const float* __restrict__ Vg, float* __restrict__ O)
{
    extern __shared__ __align__(16) float smem[];
    float* sQ  = smem;                 // 128 x 68
    float* sK  = sQ + 128*68;          // 32 x 68
    float* sV  = sK + 32*68;           // 32 x 72
    float* sPb = sV + 32*72;           // 4 warps x (32 cols x 40)

    const int bh  = blockIdx.y;
    const int qt  = blockIdx.x;
    const int tid = threadIdx.x;
    const int wid = tid >> 5;
    const int lane = tid & 31;
    const int gid = lane >> 2;
    const int tig = lane & 3;
    const int m0  = wid * 32;
    float* sP = sPb + wid * (32*40);

    const float* Qbase = Q + ((size_t)bh * SEQ + qt * 128) * HDIM;
    const float* Kbase = Kg + (size_t)bh * SEQ * HDIM;
    const float* Vbase = Vg + (size_t)bh * SEQ * HDIM;

    // stage Q (128x64), scaled by 1/sqrt(D), cvt to tf32
    {
        const float* qr = Qbase + (size_t)tid * HDIM;
#pragma unroll
        for (int i = 0; i < 16; i++) {
            float4 v = *(const float4*)(qr + i * 4);
            v.x *= 0.125f; v.y *= 0.125f; v.z *= 0.125f; v.w *= 0.125f;
            *(float4*)&QS(tid, i * 4) = cvt4(v);
        }
    }
    __syncthreads();

    float o[2][8][4];
#pragma unroll
    for (int mt = 0; mt < 2; mt++)
#pragma unroll
        for (int nt = 0; nt < 8; nt++)
#pragma unroll
            for (int i = 0; i < 4; i++) o[mt][nt][i] = 0.f;
    float mrow[2][2] = {{-INFINITY,-INFINITY},{-INFINITY,-INFINITY}};
    float lrow[2][2] = {{0.f,0.f},{0.f,0.f}};

    const int qmax_warp = qt * 128 + m0 + 31;
    const int nch = 4 * qt + 4;

    for (int ch = 0; ch < nch; ch++) {
        // stage K,V chunk (32x64), cvt to tf32
        {
            const int kr = tid >> 2, kc = (tid & 3) * 16;
            const float* kp = Kbase + (size_t)(ch * 32 + kr) * HDIM + kc;
            const float* vp = Vbase + (size_t)(ch * 32 + kr) * HDIM + kc;
#pragma unroll
            for (int i = 0; i < 4; i++) {
                *(float4*)&KS_(kr, kc + i * 4) = cvt4(*(const float4*)(kp + i * 4));
                *(float4*)&VS_(kr, kc + i * 4) = cvt4(*(const float4*)(vp + i * 4));
            }
        }
        __syncthreads();

        if (ch * 32 <= qmax_warp) {
            // ---- S = Q K^T : 32 rows x 32 keys per warp ----
            float s[2][4][4];
#pragma unroll
            for (int mt = 0; mt < 2; mt++)
#pragma unroll
                for (int nt = 0; nt < 4; nt++)
#pragma unroll
                    for (int i = 0; i < 4; i++) s[mt][nt][i] = 0.f;

#pragma unroll
            for (int ks = 0; ks < 8; ks++) {
                uint32_t a[2][4];
#pragma unroll
                for (int mt = 0; mt < 2; mt++) {
                    const int r0 = m0 + mt * 16;
                    a[mt][0] = __float_as_uint(QS(r0 + gid,     ks*8 + tig));
                    a[mt][1] = __float_as_uint(QS(r0 + gid + 8, ks*8 + tig));
                    a[mt][2] = __float_as_uint(QS(r0 + gid,     ks*8 + tig + 4));
                    a[mt][3] = __float_as_uint(QS(r0 + gid + 8, ks*8 + tig + 4));
                }
#pragma unroll
                for (int nt = 0; nt < 4; nt++) {
                    uint32_t b[2];
                    b[0] = __float_as_uint(KS_(nt*8 + gid, ks*8 + tig));
                    b[1] = __float_as_uint(KS_(nt*8 + gid, ks*8 + tig + 4));
                    mma_tf32(s[0][nt], a[0], b);
                    mma_tf32(s[1][nt], a[1], b);
                }
            }

            // ---- register online softmax ----
#pragma unroll
            for (int mt = 0; mt < 2; mt++) {
#pragma unroll
                for (int half = 0; half < 2; half++) {
                    const int qrow = qt * 128 + m0 + mt * 16 + gid + half * 8;
                    const int cb   = ch * 32 + 2 * tig;
                    float mx = -INFINITY;
#pragma unroll
                    for (int nt = 0; nt < 4; nt++) {
#pragma unroll
                        for (int ii = 0; ii < 2; ii++) {
                            const int cc = cb + nt * 8 + ii;
                            if (cc <= qrow)
                                mx = fmaxf(mx, s[mt][nt][half * 2 + ii]);
                        }
                    }
                    mx = fmaxf(mx, __shfl_xor_sync(0xffffffffu, mx, 1));
                    mx = fmaxf(mx, __shfl_xor_sync(0xffffffffu, mx, 2));
                    const float mold = mrow[mt][half];
                    const float mnew = fmaxf(mold, mx);
                    const float msafe = (mnew == -INFINITY) ? 0.f : mnew;
                    const float corr  = (mold == -INFINITY) ? 0.f : __expf(mold - msafe);
                    float sum = 0.f;
#pragma unroll
                    for (int nt = 0; nt < 4; nt++) {
#pragma unroll
                        for (int ii = 0; ii < 2; ii++) {
                            const int cc = cb + nt * 8 + ii;
                            float p = (cc <= qrow) ? __expf(s[mt][nt][half*2+ii] - msafe) : 0.f;
                            s[mt][nt][half*2+ii] = p;
                            sum += p;
                        }
                    }
                    sum += __shfl_xor_sync(0xffffffffu, sum, 1);
                    sum += __shfl_xor_sync(0xffffffffu, sum, 2);
                    lrow[mt][half] = lrow[mt][half] * corr + sum;
                    mrow[mt][half] = mnew;
#pragma unroll
                    for (int nt = 0; nt < 8; nt++) {
                        o[mt][nt][half*2+0] *= corr;
                        o[mt][nt][half*2+1] *= corr;
                    }
                }
            }

            // ---- write P (tf32-cvt'd) to per-warp buffer [col][row] stride 40 ----
#pragma unroll
            for (int mt = 0; mt < 2; mt++) {
                const int rl = mt * 16 + gid;
#pragma unroll
                for (int nt = 0; nt < 4; nt++) {
                    const int cc = nt * 8 + 2 * tig;
                    SSW(cc,     rl)     = __uint_as_float(tf32_rna(s[mt][nt][0]));
                    SSW(cc + 1, rl)     = __uint_as_float(tf32_rna(s[mt][nt][1]));
                    SSW(cc,     rl + 8) = __uint_as_float(tf32_rna(s[mt][nt][2]));
                    SSW(cc + 1, rl + 8) = __uint_as_float(tf32_rna(s[mt][nt][3]));
                }
            }
            __syncwarp();

            // ---- O += P V ----
#pragma unroll
            for (int ks = 0; ks < 4; ks++) {
                uint32_t p[2][4];
#pragma unroll
                for (int mt = 0; mt < 2; mt++) {
                    const int rl = mt * 16 + gid;
                    p[mt][0] = __float_as_uint(SSW(ks*8 + tig,     rl));
                    p[mt][1] = __float_as_uint(SSW(ks*8 + tig,     rl + 8));
                    p[mt][2] = __float_as_uint(SSW(ks*8 + tig + 4, rl));
                    p[mt][3] = __float_as_uint(SSW(ks*8 + tig + 4, rl + 8));
                }
#pragma unroll
                for (int nt = 0; nt < 8; nt++) {
                    uint32_t v[2];
                    v[0] = __float_as_uint(VS_(ks*8 + tig,     nt*8 + gid));
                    v[1] = __float_as_uint(VS_(ks*8 + tig + 4, nt*8 + gid));
                    mma_tf32(o[0][nt], p[0], v);
                    mma_tf32(o[1][nt], p[1], v);
                }
            }
        }
        __syncthreads();
    }

    // epilogue: normalize and store to [b][s][h*64+d]
    const int b = bh / HEADS, h = bh % HEADS;
#pragma unroll
    for (int mt = 0; mt < 2; mt++) {
#pragma unroll
        for (int half = 0; half < 2; half++) {
            const float inv = 1.f / lrow[mt][half];
            const int sg = qt * 128 + m0 + mt * 16 + gid + half * 8;
            float* orow = O + ((size_t)(b * SEQ + sg)) * EMB + h * HDIM;
#pragma unroll
            for (int nt = 0; nt < 8; nt++) {
                const int cc = nt * 8 + 2 * tig;
                orow[cc]     = o[mt][nt][half*2+0] * inv;
                orow[cc + 1] = o[mt][nt][half*2+1] * inv;
            }
        }
    }
}

// ---------------------------------------------------------------------------
extern "C" void kernel_launch(void* const* d_in, const int* in_sizes, int n_in,
                              void* d_out, int out_size)
{
    const float* x  = (const float*)d_in[0];
    const float* Wq = (const float*)d_in[1];
    const float* bq = (const float*)d_in[2];
    const float* Wk = (const float*)d_in[3];
    const float* bk = (const float*)d_in[4];
    const float* Wv = (const float*)d_in[5];
    const float* bv = (const float*)d_in[6];
    const float* Wo = (const float*)d_in[7];
    const float* bo = (const float*)d_in[8];
    float* out = (float*)d_out;

    float *q_ptr, *k_ptr, *v_ptr, *ao_ptr;
    cudaGetSymbolAddress((void**)&q_ptr,  g_q);
    cudaGetSymbolAddress((void**)&k_ptr,  g_k);
    cudaGetSymbolAddress((void**)&v_ptr,  g_v);
    cudaGetSymbolAddress((void**)&ao_ptr, g_ao);

    const int attn_smem = ATTN_SMEM_FLOATS * 4;
    static int attr_set = 0;
    if (!attr_set) {
        cudaFuncSetAttribute(attn_tf32,  cudaFuncAttributeMaxDynamicSharedMemorySize, attn_smem);
        cudaFuncSetAttribute(gemm_proj,  cudaFuncAttributeMaxDynamicSharedMemorySize, GEMM_SMEM_BYTES);
        cudaFuncSetAttribute(gemm_out,   cudaFuncAttributeMaxDynamicSharedMemorySize, GEMM_SMEM_BYTES);
        attr_set = 1;
    }

    dim3 gblk(256);
    dim3 pgrid(EMB / 128, MROWS / 128, 3);   // (8, 64, 3)
    gemm_proj<<<pgrid, gblk, GEMM_SMEM_BYTES>>>(x, Wq, Wk, Wv, bq, bk, bv,
                                                q_ptr, k_ptr, v_ptr);

    dim3 agrid(SEQ / 128, BATCH * HEADS);    // (16, 64)
    attn_tf32<<<agrid, 128, attn_smem>>>(q_ptr, k_ptr, v_ptr, ao_ptr);

    dim3 ogrid(EMB / 128, MROWS / 128, 1);   // (8, 64)
    gemm_out<<<ogrid, gblk, GEMM_SMEM_BYTES>>>(ao_ptr, Wo, bo, out);
}